// round 11
// baseline (speedup 1.0000x reference)
#include <cuda_runtime.h>
#include <cuda_fp16.h>
#include <cstdint>

// ============================================================================
// HelixMemory, zero-prep GEMM (in-loop A conversion + ldmatrix B):
//   out[b, 0:254]      = cm[r]   = memory[2r+2] @ F0 + memory[2r+3] @ F1
//   out[b, 254:510]    = cx[b,t] = x[b,2t] @ F0 + x[b,2t+1] @ F1
//   out[b, 510:2046]   = memory[1022:2558]
//   out[b, 2046:2558]  = x[b]
// kernel 1: conv_filters -> g_Bt[n][k] fp16 (4 MB), ~4 us.
// kernel 2: mega, 792 blocks:
//   [0,528):  GEMM tiles. A = fp32 inputs/memory via cp.async (2-stage),
//             converted to fp16 in the fragment loop (LDS.64 + cvt.f16x2 —
//             hidden under the ~4096 cyc/SMSP tensor shadow per kt).
//             B via ldmatrix. cm rows broadcast to 32 batches in epilogue.
//   [528,792): copy CTAs (tail-positioned): x passthrough + memory-tail
//             broadcast, unroll-8, ~1 MB each; backfill wave-2 slots.
// ============================================================================

namespace {
constexpr int D_       = 1024;
constexpr int KDIM     = 2048;
constexpr int OUT_ROWS = 2558;
constexpr int CM_ROWS  = 254;
constexpr int BATCH    = 32;
constexpr int SEQ      = 512;

constexpr int BM = 128, BN = 128, BK = 64;       // BK in elements (k)
constexpr int KT = KDIM / BK;                    // 32

constexpr int PITCH_AF = 72;                     // A pitch, fp32 elements
constexpr int PITCH_BH = 72;                     // B pitch, fp16 elements
constexpr int A_TILE_B = BM * PITCH_AF * 4;      // 36864 B
constexpr int B_TILE_B = BM * PITCH_BH * 2;      // 18432 B
constexpr int STAGE_B  = A_TILE_B + B_TILE_B;    // 55296 B
constexpr int SMEM_BYTES = 2 * STAGE_B;          // 110592 B -> occ 2

constexpr int GEMM_BLOCKS  = 8 * 66;             // 528
constexpr int COPY_CTAS    = 264;
constexpr int TOTAL_BLOCKS = GEMM_BLOCKS + COPY_CTAS;  // 792

// unified copy space (float4 units): passthrough then memory broadcast
constexpr int PASS_F4    = BATCH * SEQ * D_ / 4;                   // 4,194,304
constexpr int BCST_PER_B = 1536 * D_ / 4;                          // 393216
constexpr int BCST_F4    = BATCH * BCST_PER_B;                     // 12,582,912
constexpr int COPY_F4    = PASS_F4 + BCST_F4;                      // 16,777,216
constexpr int COPY_CHUNK = (COPY_F4 + COPY_CTAS - 1) / COPY_CTAS;  // 63552
}

__device__ __align__(128) __half g_Bt[D_ * KDIM];   // 4 MB, filters^T [n][k]

// ---------------------------------------------------------------------------
__device__ __forceinline__ uint32_t smem_u32(const void* p) {
    uint32_t a;
    asm("{ .reg .u64 t; cvta.to.shared.u64 t, %1; cvt.u32.u64 %0, t; }" : "=r"(a) : "l"(p));
    return a;
}
__device__ __forceinline__ void cp16(uint32_t s, const void* g) {
    asm volatile("cp.async.cg.shared.global [%0], [%1], 16;" :: "r"(s), "l"(g));
}
__device__ __forceinline__ void ldsm_x4(uint32_t* r, uint32_t addr) {
    asm volatile("ldmatrix.sync.aligned.m8n8.x4.shared.b16 {%0,%1,%2,%3}, [%4];"
                 : "=r"(r[0]), "=r"(r[1]), "=r"(r[2]), "=r"(r[3]) : "r"(addr));
}
__device__ __forceinline__ void mma_f16(float* c, const uint32_t* a, const uint32_t* b) {
    asm volatile(
        "mma.sync.aligned.m16n8k16.row.col.f32.f16.f16.f32 "
        "{%0,%1,%2,%3}, {%4,%5,%6,%7}, {%8,%9}, {%0,%1,%2,%3};"
        : "+f"(c[0]), "+f"(c[1]), "+f"(c[2]), "+f"(c[3])
        : "r"(a[0]), "r"(a[1]), "r"(a[2]), "r"(a[3]), "r"(b[0]), "r"(b[1]));
}
__device__ __forceinline__ uint32_t pack_h2(float x, float y) {
    __half2 h = __floats2half2_rn(x, y);
    return *reinterpret_cast<uint32_t*>(&h);
}

// ---------------------------------------------------------------------------
// conv_filters: g_Bt[n][k] = fp16(F[k][n])
// ---------------------------------------------------------------------------
__global__ __launch_bounds__(256) void conv_filters(const float* __restrict__ F)
{
    __shared__ float tile[64][33];
    const int n0 = blockIdx.x * 32;
    const int k0 = blockIdx.y * 64;
    const int tx = threadIdx.x, ty = threadIdx.y;       // 32 x 8
    #pragma unroll
    for (int i = ty; i < 64; i += 8)
        tile[i][tx] = F[(size_t)(k0 + i) * D_ + n0 + tx];
    __syncthreads();
    uint32_t* bt = reinterpret_cast<uint32_t*>(g_Bt);
    #pragma unroll
    for (int i = ty; i < 32; i += 8)
        bt[(size_t)(n0 + i) * (KDIM / 2) + k0 / 2 + tx] =
            pack_h2(tile[2 * tx][i], tile[2 * tx + 1][i]);
}

// ---------------------------------------------------------------------------
// copy CTA body: unified index space (passthrough + memory broadcast),
// unroll-8 batched loads for MLP.
// ---------------------------------------------------------------------------
__device__ __forceinline__ void copy_body(
    int cid, const float* __restrict__ inputs, const float* __restrict__ memory,
    float* __restrict__ out)
{
    const float4* in4  = reinterpret_cast<const float4*>(inputs);
    const float4* mem4 = reinterpret_cast<const float4*>(memory) + 1022 * (D_ / 4);
    float4*       out4 = reinterpret_cast<float4*>(out);

    const int base = cid * COPY_CHUNK;
    const int end  = (base + COPY_CHUNK < COPY_F4) ? base + COPY_CHUNK : COPY_F4;

    for (int t = base + threadIdx.x; t < end; t += 256 * 8) {
        float4 v[8];
        size_t dj[8];
        bool ok[8];
        #pragma unroll
        for (int u = 0; u < 8; ++u) {
            const int idx = t + u * 256;
            ok[u] = (idx < end);
            if (ok[u]) {
                if (idx < PASS_F4) {
                    const int b = idx >> 17;                 // / 131072
                    const int rem = idx & 131071;
                    v[u]  = in4[idx];
                    dj[u] = (size_t)b * (OUT_ROWS * D_ / 4) + 2046 * (D_ / 4) + rem;
                } else {
                    const int j = idx - PASS_F4;
                    const int b = j / BCST_PER_B;
                    const int rem = j - b * BCST_PER_B;
                    v[u]  = mem4[rem];
                    dj[u] = (size_t)b * (OUT_ROWS * D_ / 4) + 510 * (D_ / 4) + rem;
                }
            }
        }
        #pragma unroll
        for (int u = 0; u < 8; ++u)
            if (ok[u]) out4[dj[u]] = v[u];
    }
}

// ---------------------------------------------------------------------------
// mega: blocks [0,528) = GEMM tiles; [528,792) = copy CTAs (tail-filling).
// ---------------------------------------------------------------------------
__global__ __launch_bounds__(256, 2) void mega(
    const float* __restrict__ inputs, const float* __restrict__ memory,
    float* __restrict__ out)
{
    const int blk = blockIdx.x;
    if (blk >= GEMM_BLOCKS) {
        copy_body(blk - GEMM_BLOCKS, inputs, memory, out);
        return;
    }
    const int bm = blk >> 3;                    // 0..65
    const int bn = blk & 7;
    const int n0 = bn * BN;

    extern __shared__ char smem[];
    const uint32_t sbase = smem_u32(smem);

    const int tid  = threadIdx.x;
    const int wid  = tid >> 5;
    const int lane = tid & 31;
    const int g    = lane >> 2;
    const int t    = lane & 3;
    const int wm   = wid & 3;                   // 4 warps x 32 rows
    const int wn   = wid >> 2;                  // 2 warps x 64 cols

    // ldmatrix lane->row mapping for B
    const int b_row = (lane & 7) + ((lane >> 4) << 3);   // n within 16
    const int b_k   = ((lane >> 3) & 1) << 3;            // k offset 0/8
    const uint32_t boff0 = (uint32_t)A_TILE_B +
                           (uint32_t)((wn * 64 + b_row) * PITCH_BH + b_k) * 2;

    // A: fp32 source (inputs for bm<64, memory rows for bm>=64)
    const float* Abase = (bm < 64)
        ? (inputs + (size_t)bm * BM * KDIM)
        : (memory + 2 * D_ + (size_t)(bm - 64) * BM * KDIM);

    auto issue = [&](int kt) {
        const int s = kt & 1;
        const uint32_t sA = sbase + (uint32_t)s * STAGE_B;
        const uint32_t sB = sA + (uint32_t)A_TILE_B;
        const int k0 = kt * BK;
        #pragma unroll
        for (int i = 0; i < 8; ++i) {           // A: 128 rows x 64 f32 = 2048 chunks
            const int q   = tid + 256 * i;
            const int row = q >> 4;
            const int c   = q & 15;
            cp16(sA + (uint32_t)(row * PITCH_AF + c * 4) * 4,
                 Abase + (size_t)row * KDIM + k0 + c * 4);
        }
        #pragma unroll
        for (int i = 0; i < 4; ++i) {           // B: 128 rows x 64 f16 = 1024 chunks
            const int q   = tid + 256 * i;
            const int row = q >> 3;
            const int c   = q & 7;
            cp16(sB + (uint32_t)(row * PITCH_BH + c * 8) * 2,
                 g_Bt + (size_t)(n0 + row) * KDIM + k0 + c * 8);
        }
        asm volatile("cp.async.commit_group;" ::: "memory");
    };

    float c[2][8][4] = {};

    issue(0);

    for (int kt = 0; kt < KT; ++kt) {
        // only the group for stage kt&1 can be pending here
        asm volatile("cp.async.wait_group 0;" ::: "memory");
        __syncthreads();

        // safe: stage (kt+1)&1 was last read in iteration kt-1, and every
        // warp passed this barrier since then.
        if (kt + 1 < KT) issue(kt + 1);

        const int s = kt & 1;
        const float*   As  = reinterpret_cast<const float*>(smem + s * STAGE_B);
        const uint32_t stg = sbase + (uint32_t)s * STAGE_B;

        #pragma unroll
        for (int ks = 0; ks < 4; ++ks) {        // 4 x k16 = BK 64
            uint32_t a[2][4];
            #pragma unroll
            for (int mt = 0; mt < 2; ++mt) {    // fp32 -> fp16 in registers
                const float* ap = As + (wm * 32 + mt * 16 + g) * PITCH_AF + ks * 16 + 2 * t;
                float2 v0 = *reinterpret_cast<const float2*>(ap);
                float2 v1 = *reinterpret_cast<const float2*>(ap + 8 * PITCH_AF);
                float2 v2 = *reinterpret_cast<const float2*>(ap + 8);
                float2 v3 = *reinterpret_cast<const float2*>(ap + 8 * PITCH_AF + 8);
                a[mt][0] = pack_h2(v0.x, v0.y);
                a[mt][1] = pack_h2(v1.x, v1.y);
                a[mt][2] = pack_h2(v2.x, v2.y);
                a[mt][3] = pack_h2(v3.x, v3.y);
            }
            uint32_t bf[8][2];
            #pragma unroll
            for (int nb = 0; nb < 4; ++nb) {    // B via ldmatrix, 4 x n16
                uint32_t r[4];
                ldsm_x4(r, stg + boff0 + (uint32_t)(nb * 16 * PITCH_BH) * 2
                           + (uint32_t)(ks * 16) * 2);
                bf[2 * nb][0]     = r[0];
                bf[2 * nb][1]     = r[1];
                bf[2 * nb + 1][0] = r[2];
                bf[2 * nb + 1][1] = r[3];
            }
            #pragma unroll
            for (int mt = 0; mt < 2; ++mt)
                #pragma unroll
                for (int nt = 0; nt < 8; ++nt)
                    mma_f16(c[mt][nt], a[mt], bf[nt]);
        }
        __syncthreads();
    }

    // ---- epilogue -----------------------------------------------------------
    #pragma unroll
    for (int mt = 0; mt < 2; ++mt) {
        #pragma unroll
        for (int half = 0; half < 2; ++half) {
            const int rloc = wm * 32 + mt * 16 + half * 8 + g;
            if (bm < 64) {
                const int rr = bm * BM + rloc;
                const int b = rr >> 8, tt = rr & 255;
                float* dst = out + ((size_t)b * OUT_ROWS + 254 + tt) * D_ + n0 + wn * 64;
                #pragma unroll
                for (int nt = 0; nt < 8; ++nt) {
                    float2 v = make_float2(c[mt][nt][half * 2], c[mt][nt][half * 2 + 1]);
                    *reinterpret_cast<float2*>(dst + nt * 8 + t * 2) = v;
                }
            } else {
                const int rr = (bm - 64) * BM + rloc;   // compressed-memory row
                if (rr < CM_ROWS) {
                    float* dst0 = out + (size_t)rr * D_ + n0 + wn * 64;
                    #pragma unroll
                    for (int nt = 0; nt < 8; ++nt) {
                        float2 v = make_float2(c[mt][nt][half * 2], c[mt][nt][half * 2 + 1]);
                        float* dp = dst0 + nt * 8 + t * 2;
                        for (int b = 0; b < BATCH; ++b)
                            *reinterpret_cast<float2*>(dp + (size_t)b * OUT_ROWS * D_) = v;
                    }
                }
            }
        }
    }
}

// ---------------------------------------------------------------------------
extern "C" void kernel_launch(void* const* d_in, const int* in_sizes, int n_in,
                              void* d_out, int out_size)
{
    const float* inputs  = (const float*)d_in[0];  // (32, 512, 1024)
    const float* memory  = (const float*)d_in[1];  // (2558, 1024)
    const float* filters = (const float*)d_in[2];  // (2, 1024, 1024)
    float* out = (float*)d_out;                    // (32, 2558, 1024)

    cudaFuncSetAttribute(mega, cudaFuncAttributeMaxDynamicSharedMemorySize,
                         SMEM_BYTES);

    // only prep: B^T fp16 (4 MB)
    conv_filters<<<dim3(D_ / 32, KDIM / 64), dim3(32, 8)>>>(filters);

    // fused GEMM (fp32 A converted in-loop) + overlapped copies
    mega<<<TOTAL_BLOCKS, 256, SMEM_BYTES>>>(inputs, memory, out);
}